// round 9
// baseline (speedup 1.0000x reference)
#include <cuda_runtime.h>
#include <cuda_bf16.h>
#include <cstdint>

// Problem dims (fixed by setup_inputs)
#define M_DIM 8192   // B*S
#define N_DIM 4096   // out_features
#define K_DIM 4096   // in_features
#define GS    128
#define NGRP  (K_DIM / GS)        // 32
#define G_TOT (N_DIM * NGRP)      // 131072
#define P_DIM 8

// GEMM tiling
#define BM 128
#define BN 128
#define BK 32
#define KT (K_DIM / BK)           // 128 k-tiles; 4 per scale-group
#define STAGES 4
#define TILE_ELEMS (BM * BK)      // 4096 bf16 per array
#define STAGE_ELEMS (3 * TILE_ELEMS)   // Ah, Al, S = 12288 bf16 = 24KB
#define GROUP_M 16

#define SCALE_PITCH 36            // f32 words per column row (bank-spread, 16B-aligned)
#define SMEM_SCALE_OFF (STAGES * STAGE_ELEMS * 2)          // 98304 B
#define SMEM_TOTAL (SMEM_SCALE_OFF + BN * SCALE_PITCH * 4) // +18432 = 116736 B

// -------- static device scratch (no cudaMalloc allowed) --------
__device__ float g_blend[G_TOT];
__device__ __nv_bfloat16 g_S[(size_t)N_DIM * K_DIM];   // signs, exact in bf16
__device__ __nv_bfloat16 g_Xh[(size_t)M_DIM * K_DIM];
__device__ __nv_bfloat16 g_Xl[(size_t)M_DIM * K_DIM];

// -------- kernel 1: blend per-profile scales via routing --------
__global__ void blend_kernel(const float* __restrict__ ps, const float* __restrict__ routing) {
    int g = blockIdx.x * blockDim.x + threadIdx.x;
    if (g >= G_TOT) return;
    float acc = 0.f;
#pragma unroll
    for (int p = 0; p < P_DIM; ++p) acc += routing[p] * ps[(size_t)p * G_TOT + g];
    g_blend[g] = acc;
}

// -------- kernel 2: signs f32 -> bf16 (exact: values are +/-1) --------
__global__ void build_s_kernel(const float* __restrict__ signs) {
    size_t idx4 = ((size_t)blockIdx.x * blockDim.x + threadIdx.x) * 4;
    float4 v = *reinterpret_cast<const float4*>(signs + idx4);
    union { __nv_bfloat16 b[4]; uint2 u; } o;
    o.b[0] = __float2bfloat16(v.x); o.b[1] = __float2bfloat16(v.y);
    o.b[2] = __float2bfloat16(v.z); o.b[3] = __float2bfloat16(v.w);
    *reinterpret_cast<uint2*>(g_S + idx4) = o.u;
}

// -------- kernel 3: split x into bf16 hi + bf16 residual --------
__global__ void split_x_kernel(const float* __restrict__ X) {
    size_t idx4 = ((size_t)blockIdx.x * blockDim.x + threadIdx.x) * 4;
    float4 v = *reinterpret_cast<const float4*>(X + idx4);
    float f[4] = { v.x, v.y, v.z, v.w };
    union { __nv_bfloat16 b[4]; uint2 u; } uh, ul;
#pragma unroll
    for (int e = 0; e < 4; ++e) {
        __nv_bfloat16 h = __float2bfloat16(f[e]);
        uh.b[e] = h;
        ul.b[e] = __float2bfloat16(f[e] - __bfloat162float(h));
    }
    *reinterpret_cast<uint2*>(g_Xh + idx4) = uh.u;
    *reinterpret_cast<uint2*>(g_Xl + idx4) = ul.u;
}

// -------- GEMM helpers --------
__device__ __forceinline__ void ldsm_x4(uint32_t (&r)[4], uint32_t addr) {
    asm volatile("ldmatrix.sync.aligned.m8n8.x4.shared.b16 {%0,%1,%2,%3}, [%4];"
                 : "=r"(r[0]), "=r"(r[1]), "=r"(r[2]), "=r"(r[3]) : "r"(addr));
}
__device__ __forceinline__ void mma_bf16(float (&d)[4], const uint32_t (&a)[4],
                                         uint32_t b0, uint32_t b1) {
    asm volatile("mma.sync.aligned.m16n8k16.row.col.f32.bf16.bf16.f32 "
                 "{%0,%1,%2,%3},{%4,%5,%6,%7},{%8,%9},{%0,%1,%2,%3};"
                 : "+f"(d[0]), "+f"(d[1]), "+f"(d[2]), "+f"(d[3])
                 : "r"(a[0]), "r"(a[1]), "r"(a[2]), "r"(a[3]), "r"(b0), "r"(b1));
}
__device__ __forceinline__ void cp_async16(uint32_t smem_dst, const void* gmem_src) {
    asm volatile("cp.async.cg.shared.global [%0], [%1], 16;" :: "r"(smem_dst), "l"(gmem_src));
}
__device__ __forceinline__ void cp_commit() { asm volatile("cp.async.commit_group;"); }
__device__ __forceinline__ void cp_wait2()  { asm volatile("cp.async.wait_group 2;"); }
__device__ __forceinline__ void stcs_f2(float* p, float a, float b) {
    asm volatile("st.global.cs.v2.f32 [%0], {%1,%2};" :: "l"(p), "f"(a), "f"(b) : "memory");
}

// Swizzle for 64B rows (BK=32 bf16): 16B-chunk c in [0,4) XOR'd with (row>>1)&3.
// Bank proof: bank = (16r + 4(c^((r>>1)&3))) mod 32; any LDSM phase (8 consecutive
// rows, fixed c) covers all 32 banks exactly once. Conflict-free for fill + LDSM.
__device__ __forceinline__ int sw32(int r, int c) {
    return r * BK + ((c ^ ((r >> 1) & 3)) << 3);   // bf16-element offset
}

// One stage: 3 arrays (Ah, Al, S), each BM x BK bf16 = 512 16B-chunks -> 2/thread.
__device__ __forceinline__ void load_stage(uint32_t sbase, int tid, int bm, int bn, int k0) {
#pragma unroll
    for (int i = 0; i < 2; ++i) {
        int idx = tid * 2 + i;            // [0,512)
        int row = idx >> 2, c = idx & 3;
        uint32_t soff = (uint32_t)sw32(row, c) * 2;
        size_t ga = (size_t)(bm + row) * K_DIM + k0 + c * 8;
        size_t gb = (size_t)(bn + row) * K_DIM + k0 + c * 8;
        cp_async16(sbase + 0 * TILE_ELEMS * 2 + soff, g_Xh + ga);
        cp_async16(sbase + 1 * TILE_ELEMS * 2 + soff, g_Xl + ga);
        cp_async16(sbase + 2 * TILE_ELEMS * 2 + soff, g_S  + gb);
    }
}

// -------- kernel 4: group-scaled sign GEMM --------
// out[m,n] = sum_g scale[n,g] * ( (xh+xl)[m,k in g] . sign[n,k in g] )
__global__ void __launch_bounds__(256, 1)
gemm_kernel(float* __restrict__ O) {
    extern __shared__ __align__(16) char smem[];           // 116736 B
    __nv_bfloat16* smem_bf = reinterpret_cast<__nv_bfloat16*>(smem);
    float* s_scale = reinterpret_cast<float*>(smem + SMEM_SCALE_OFF);

    const int tid  = threadIdx.x;
    const int lane = tid & 31, warp = tid >> 5;
    const int wm = warp >> 1, wn = warp & 1;        // 4x2 warps, 32x64 warp tiles

    // grouped rasterization for L2 reuse: S re-streamed 64/GROUP_M = 4x total;
    // wave working set ~41MB < L2 (126MB).
    const int TN = N_DIM / BN;                      // 32
    int pid = blockIdx.x;
    int npg = GROUP_M * TN;                         // 512
    int gid = pid / npg;
    int pm  = gid * GROUP_M + (pid % GROUP_M);
    int pn  = (pid % npg) / GROUP_M;
    const int bm = pm * BM, bn = pn * BN;

    float accO[2][8][4], accG[2][8][4];
#pragma unroll
    for (int mt = 0; mt < 2; ++mt)
#pragma unroll
        for (int nt = 0; nt < 8; ++nt)
#pragma unroll
            for (int e = 0; e < 4; ++e) { accO[mt][nt][e] = 0.f; accG[mt][nt][e] = 0.f; }

    const uint32_t smem_u32 = (uint32_t)__cvta_generic_to_shared(smem_bf);

    // per-thread LDSM byte offsets within a stage, per (fragment, k16-half)
    uint32_t aOff[2][2], bOff[4][2];
#pragma unroll
    for (int mt = 0; mt < 2; ++mt) {
        int r = wm * 32 + mt * 16 + (lane & 15);
#pragma unroll
        for (int ks = 0; ks < 2; ++ks)
            aOff[mt][ks] = (uint32_t)sw32(r, ks * 2 + (lane >> 4)) * 2;
    }
#pragma unroll
    for (int p = 0; p < 4; ++p) {
        int rr = wn * 64 + p * 16 + ((lane >> 4) & 1) * 8 + (lane & 7);
#pragma unroll
        for (int ks = 0; ks < 2; ++ks)
            bOff[p][ks] = (uint32_t)sw32(rr, ks * 2 + ((lane >> 3) & 1)) * 2;
    }

    // prologue: fill STAGES-1 = 3 pipeline stages
    load_stage(smem_u32 + 0 * STAGE_ELEMS * 2, tid, bm, bn, 0);
    cp_commit();
    load_stage(smem_u32 + 1 * STAGE_ELEMS * 2, tid, bm, bn, BK);
    cp_commit();
    load_stage(smem_u32 + 2 * STAGE_ELEMS * 2, tid, bm, bn, 2 * BK);
    cp_commit();

    // stage the CTA's scale tile: s_scale[col * 36 + g] = blend[(bn+col)*32 + g]
    // (write-once; visible to all after the first mainloop barrier)
#pragma unroll
    for (int i = 0; i < 4; ++i) {
        int q = tid + i * 256;              // [0,1024)
        int col = q >> 3, qi = q & 7;
        float4 v = *reinterpret_cast<const float4*>(g_blend + (size_t)(bn + col) * NGRP + qi * 4);
        *reinterpret_cast<float4*>(s_scale + col * SCALE_PITCH + qi * 4) = v;
    }

    const int cb = wn * 64 + (lane & 3) * 2;   // this thread's base output column (in-CTA)

#pragma unroll 1
    for (int kt = 0; kt < KT; ++kt) {
        // Single barrier per iteration.
        // RAW: stage kt committed >=3 iters ago; wait_group 2 + barrier publish it.
        // WAR: slot (kt+3)%4 held stage kt-1, whose LDSMs completed (register
        //      scoreboard) before each thread reached THIS barrier; loads below
        //      are issued only after it. Safe without an end-of-loop barrier.
        cp_wait2();
        __syncthreads();

        if (kt + 3 < KT)
            load_stage(smem_u32 + (uint32_t)((kt + 3) % STAGES) * STAGE_ELEMS * 2,
                       tid, bm, bn, (kt + 3) * BK);
        cp_commit();

        const uint32_t sb = smem_u32 + (uint32_t)(kt % STAGES) * STAGE_ELEMS * 2;
#pragma unroll
        for (int ks = 0; ks < 2; ++ks) {
            uint32_t ah[2][4], al[2][4], s[4][4];
#pragma unroll
            for (int mt = 0; mt < 2; ++mt) {
                ldsm_x4(ah[mt], sb + 0 * TILE_ELEMS * 2 + aOff[mt][ks]);
                ldsm_x4(al[mt], sb + 1 * TILE_ELEMS * 2 + aOff[mt][ks]);
            }
#pragma unroll
            for (int p = 0; p < 4; ++p)
                ldsm_x4(s[p], sb + 2 * TILE_ELEMS * 2 + bOff[p][ks]);
#pragma unroll
            for (int mt = 0; mt < 2; ++mt)
#pragma unroll
                for (int p = 0; p < 4; ++p) {
                    mma_bf16(accG[mt][2 * p],     ah[mt], s[p][0], s[p][1]);
                    mma_bf16(accG[mt][2 * p],     al[mt], s[p][0], s[p][1]);
                    mma_bf16(accG[mt][2 * p + 1], ah[mt], s[p][2], s[p][3]);
                    mma_bf16(accG[mt][2 * p + 1], al[mt], s[p][2], s[p][3]);
                }
        }

        // group boundary: fold accG into accO with the group's per-column scale.
        // LDS pattern: 4 distinct addresses/warp (stride 72 words -> banks +8 apart),
        // 8-lane broadcast groups -> conflict-free.
        if ((kt & 3) == 3) {
            int g = kt >> 2;
#pragma unroll
            for (int nt = 0; nt < 8; ++nt) {
                float s0 = s_scale[(cb + nt * 8 + 0) * SCALE_PITCH + g];
                float s1 = s_scale[(cb + nt * 8 + 1) * SCALE_PITCH + g];
#pragma unroll
                for (int mt = 0; mt < 2; ++mt) {
                    accO[mt][nt][0] += s0 * accG[mt][nt][0];
                    accO[mt][nt][1] += s1 * accG[mt][nt][1];
                    accO[mt][nt][2] += s0 * accG[mt][nt][2];
                    accO[mt][nt][3] += s1 * accG[mt][nt][3];
                    accG[mt][nt][0] = 0.f; accG[mt][nt][1] = 0.f;
                    accG[mt][nt][2] = 0.f; accG[mt][nt][3] = 0.f;
                }
            }
        }
    }

    // epilogue: coalesced streaming stores (evict-first: output is write-once,
    // never re-read -> don't let 134MB of writeback evict the S/X L2 working set)
#pragma unroll
    for (int mt = 0; mt < 2; ++mt)
#pragma unroll
        for (int nt = 0; nt < 8; ++nt) {
            int row = bm + wm * 32 + mt * 16 + (lane >> 2);
            int col = bn + wn * 64 + nt * 8 + (lane & 3) * 2;
            stcs_f2(O + (size_t)row * N_DIM + col,       accO[mt][nt][0], accO[mt][nt][1]);
            stcs_f2(O + (size_t)(row + 8) * N_DIM + col, accO[mt][nt][2], accO[mt][nt][3]);
        }
}

extern "C" void kernel_launch(void* const* d_in, const int* in_sizes, int n_in,
                              void* d_out, int out_size) {
    const float* x       = (const float*)d_in[0];   // [4,2048,4096] f32
    const float* signs   = (const float*)d_in[1];   // [4096,4096] f32 (+/-1)
    const float* ps      = (const float*)d_in[2];   // [8,131072] f32
    const float* routing = (const float*)d_in[3];   // [8] f32
    float* out = (float*)d_out;                     // [4,2048,4096] f32

    // Unconditional host-side config (no static guards); capture-safe, idempotent.
    cudaFuncSetAttribute(gemm_kernel, cudaFuncAttributeMaxDynamicSharedMemorySize, SMEM_TOTAL);

    blend_kernel<<<(G_TOT + 255) / 256, 256>>>(ps, routing);
    build_s_kernel<<<(int)(((size_t)N_DIM * K_DIM / 4) / 256), 256>>>(signs);
    split_x_kernel<<<(int)(((size_t)M_DIM * K_DIM / 4) / 256), 256>>>(x);

    int grid = (M_DIM / BM) * (N_DIM / BN);   // 2048 CTAs, grouped raster
    gemm_kernel<<<grid, 256, SMEM_TOTAL>>>(out);
}